// round 14
// baseline (speedup 1.0000x reference)
#include <cuda_runtime.h>
#include <math.h>

#define NT   300
#define NCC  80
#define IMGS 640.0f

#define TOTAL_BLOCKS 882           // 6 blocks / SM
#define BLOCK 256                  // 8 warps -> 48 warps/SM resident
#define OBJ_TOTAL4 100800          // float4 count across all obj channels

// accumulators: [0..2]=sp  [3..5]=objsub  [6..8]=box  [9..11]=cls  [12..14]=nkeep
__device__ double g_acc[16] = {0};
__device__ unsigned int g_done = 0;

__constant__ float c_anchors[3][3][2] = {
    {{10.f,13.f},{16.f,30.f},{33.f,23.f}},
    {{30.f,61.f},{62.f,45.f},{59.f,119.f}},
    {{116.f,90.f},{156.f,198.f},{373.f,326.f}}
};
__constant__ float c_ranchors[3][3][2] = {
    {{1.f/10.f,1.f/13.f},{1.f/16.f,1.f/30.f},{1.f/33.f,1.f/23.f}},
    {{1.f/30.f,1.f/61.f},{1.f/62.f,1.f/45.f},{1.f/59.f,1.f/119.f}},
    {{1.f/116.f,1.f/90.f},{1.f/156.f,1.f/198.f},{1.f/373.f,1.f/326.f}}
};
__constant__ float c_stride[3] = {8.f, 16.f, 32.f};
__constant__ int   c_G[3]      = {80, 40, 20};

__device__ __forceinline__ float sigmoidf(float x) {
    return 1.0f / (1.0f + __expf(-x));
}
// sum of softplus over a float4, one log for four elements
__device__ __forceinline__ float sp4(const float4 v) {
    float m = fmaxf(v.x, 0.f) + fmaxf(v.y, 0.f) + fmaxf(v.z, 0.f) + fmaxf(v.w, 0.f);
    float pr = (1.f + __expf(-fabsf(v.x))) * (1.f + __expf(-fabsf(v.y)))
             * (1.f + __expf(-fabsf(v.z))) * (1.f + __expf(-fabsf(v.w)));
    return m + __logf(pr);
}

template<int GG4>
__device__ __forceinline__ float obj_elem(const float* __restrict__ pred, int j) {
    int plane = j / GG4;              // compile-time divisor
    int w4 = j - plane * GG4;
    const float4 v = *(const float4*)(pred + (long)plane * (340 * GG4) + 4 * w4);
    return sp4(v);
}

__global__ void __launch_bounds__(BLOCK)
fused_loss_kernel(const float* __restrict__ p0,
                  const float* __restrict__ p1,
                  const float* __restrict__ p2,
                  const float* __restrict__ tgt,
                  float* __restrict__ out)
{
    const int tid  = threadIdx.x;
    const int bx   = blockIdx.x;
    const int warp = tid >> 5, lane = tid & 31;

    __shared__ float  scx[NT], scy[NT], sgw[NT], sgh[NT];   // normalized
    __shared__ short  sbi[NT], scls[NT];
    __shared__ unsigned char sgi[3][NT], sgj[3][NT];
    __shared__ unsigned short skeep[NT];                     // 9 bits: sc*3+a
    __shared__ double sacc[15];

    if (tid < 15) sacc[tid] = 0.0;

    // ---------------- Phase 0: stage targets ----------------
    for (int n = tid; n < NT; n += BLOCK) {
        float bi = tgt[n * 6 + 0];
        float cl = tgt[n * 6 + 1];
        float tx = tgt[n * 6 + 2];
        float ty = tgt[n * 6 + 3];
        float tw = tgt[n * 6 + 4];
        float th = tgt[n * 6 + 5];
        sbi[n] = (short)bi; scls[n] = (short)cl;
        scx[n] = tx; scy[n] = ty; sgw[n] = tw; sgh[n] = th;
        float gw = tw * IMGS, gh = th * IMGS;
        unsigned bits = 0;
        #pragma unroll
        for (int sc = 0; sc < 3; sc++) {
            const int G = c_G[sc];
            int gi = (int)(tx * (float)G); gi = min(max(gi, 0), G - 1);
            int gj = (int)(ty * (float)G); gj = min(max(gj, 0), G - 1);
            sgi[sc][n] = (unsigned char)gi;
            sgj[sc][n] = (unsigned char)gj;
            #pragma unroll
            for (int a = 0; a < 3; a++) {
                float rw = gw * c_ranchors[sc][a][0];
                float rh = gh * c_ranchors[sc][a][1];
                if (rw < 4.f && rw > 0.25f && rh < 4.f && rh > 0.25f)
                    bits |= (1u << (sc * 3 + a));
            }
        }
        skeep[n] = (unsigned short)bits;
    }
    __syncthreads();

    // ---------------- Phase A: one (scale,anchor,target) unit per warp --------
    const int u = warp * TOTAL_BLOCKS + bx;   // unit id, spread across blocks
    int sc = 0, pa = 0, pn = 0, pb = 0, pcls = 0;
    bool kept = false;
    float v0 = 0.f, v1 = 0.f, v2 = 0.f;
    if (u < 2700) {
        sc = u / 900;
        int r = u - sc * 900;
        pa = r / NT; pn = r - pa * NT;
        if (skeep[pn] & (1u << (sc * 3 + pa))) {
            kept = true;
            pb = sbi[pn]; pcls = scls[pn];
            const float* pred = (sc == 0) ? p0 : ((sc == 1) ? p1 : p2);
            const int G  = c_G[sc];
            const int GG = G * G;
            const int gi = sgi[sc][pn], gj = sgj[sc][pn];
            const float* base = pred + ((long)pb * 255 + (long)pa * 85) * GG
                                     + (long)gj * G + gi;
            v0 = __ldg(base + (long)lane * GG);
            v1 = __ldg(base + (long)(lane + 32) * GG);
            v2 = (lane < 21) ? __ldg(base + (long)(lane + 64) * GG) : 0.0f;
        }
    }

    // ---------------- Phase B: obj softplus sweep (<=1 float4/thread) ---------
    {
        float osum[3] = {0.f, 0.f, 0.f};
        int i = bx * BLOCK + tid;             // [0, 225792)
        if (i < OBJ_TOTAL4) {
            if (i < 76800)       osum[0] += obj_elem<1600>(p0, i);
            else if (i < 96000)  osum[1] += obj_elem<400>(p1, i - 76800);
            else                 osum[2] += obj_elem<100>(p2, i - 96000);
        }
        #pragma unroll
        for (int s = 0; s < 3; s++) {
            #pragma unroll
            for (int o = 16; o > 0; o >>= 1)
                osum[s] += __shfl_down_sync(0xFFFFFFFF, osum[s], o);
            if (lane == 0 && osum[s] != 0.f) atomicAdd(&sacc[s], (double)osum[s]);
        }
    }

    // ---------------- Phase C: consume gather ----------------
    if (kept) {
        const int   G  = c_G[sc];
        const float stride = c_stride[sc];
        const int gi = sgi[sc][pn], gj = sgj[sc][pn];

        // lane-parallel dedup: any earlier kept target mapping to same cell?
        bool notfirst = false;
        for (int m2b = 0; m2b < pn; m2b += 32) {
            int m2 = m2b + lane;
            bool m = false;
            if (m2 < pn && (skeep[m2] & (1u << (sc * 3 + pa))) &&
                sbi[m2] == pb && sgi[sc][m2] == gi && sgj[sc][m2] == gj)
                m = true;
            if (__any_sync(0xFFFFFFFF, m)) { notfirst = true; break; }
        }

        // cls BCE: per-lane product-of-(1+e^-|x|) + one log
        float mx = 0.f, pr = 1.f, sub = 0.f;
        if (lane >= 5) {
            mx += fmaxf(v0, 0.f);
            pr *= (1.f + __expf(-fabsf(v0)));
            if (lane - 5 == pcls) sub += v0;
        }
        mx += fmaxf(v1, 0.f);
        pr *= (1.f + __expf(-fabsf(v1)));
        if (lane + 27 == pcls) sub += v1;
        if (lane < 21) {
            mx += fmaxf(v2, 0.f);
            pr *= (1.f + __expf(-fabsf(v2)));
            if (lane + 59 == pcls) sub += v2;
        }
        float csum = mx + __logf(pr) - sub;
        #pragma unroll
        for (int o = 16; o > 0; o >>= 1)
            csum += __shfl_down_sync(0xFFFFFFFF, csum, o);

        float obj = __shfl_sync(0xFFFFFFFF, v0, 0);
        float px  = __shfl_sync(0xFFFFFFFF, v0, 1);
        float py  = __shfl_sync(0xFFFFFFFF, v0, 2);
        float pw  = __shfl_sync(0xFFFFFFFF, v0, 3);
        float ph  = __shfl_sync(0xFFFFFFFF, v0, 4);

        if (lane == 0) {
            float cx = scx[pn] * (float)G;
            float cy = scy[pn] * (float)G;
            float pcx = sigmoidf(px) + (float)gi;
            float pcy = sigmoidf(py) + (float)gj;
            float aw = c_anchors[sc][pa][0] / stride;
            float ah = c_anchors[sc][pa][1] / stride;
            float pbw = __expf(fminf(fmaxf(pw, -4.0f), 4.0f)) * aw;
            float pbh = __expf(fminf(fmaxf(ph, -4.0f), 4.0f)) * ah;

            float b1x0 = (pcx - pbw * 0.5f) * stride;
            float b1y0 = (pcy - pbh * 0.5f) * stride;
            float b1x1 = (pcx + pbw * 0.5f) * stride;
            float b1y1 = (pcy + pbh * 0.5f) * stride;

            float tgw = sgw[pn] * (float)G;
            float tgh = sgh[pn] * (float)G;
            float b2x0 = (cx - tgw * 0.5f) * stride;
            float b2y0 = (cy - tgh * 0.5f) * stride;
            float b2x1 = (cx + tgw * 0.5f) * stride;
            float b2y1 = (cy + tgh * 0.5f) * stride;

            const float eps = 1e-7f;
            float w1 = b1x1 - b1x0, h1 = b1y1 - b1y0;
            float w2 = b2x1 - b2x0, h2 = b2y1 - b2y0;
            float ix = fmaxf(fminf(b1x1, b2x1) - fmaxf(b1x0, b2x0), 0.0f);
            float iy = fmaxf(fminf(b1y1, b2y1) - fmaxf(b1y0, b2y0), 0.0f);
            float inter = ix * iy;
            float uni = w1 * h1 + w2 * h2 - inter + eps;
            float iou = inter / uni;
            float cw = fmaxf(b1x1, b2x1) - fminf(b1x0, b2x0);
            float ch = fmaxf(b1y1, b2y1) - fminf(b1y0, b2y0);
            float c2 = cw * cw + ch * ch + eps;
            float dx = b2x0 + b2x1 - b1x0 - b1x1;
            float dy = b2y0 + b2y1 - b1y0 - b1y1;
            float rho2 = (dx * dx + dy * dy) * 0.25f;
            const float k4pi2 = 4.0f / (float)(M_PI * M_PI);
            float da = atanf(w2 / (h2 + eps)) - atanf(w1 / (h1 + eps));
            float vv = k4pi2 * da * da;
            float alpha = vv / (vv - iou + (1.0f + eps));
            float ciou = iou - (rho2 / c2 + vv * alpha);

            atomicAdd(&sacc[12 + sc], 1.0);
            atomicAdd(&sacc[6 + sc],  (double)(1.0f - ciou));
            atomicAdd(&sacc[9 + sc],  (double)csum);
            if (!notfirst) atomicAdd(&sacc[3 + sc], (double)obj);
        }
    }
    __syncthreads();

    // ---------------- tid0-only publish + finalize (single fence per block) ---
    if (tid == 0) {
        #pragma unroll
        for (int i2 = 0; i2 < 15; i2++) {
            double vs = sacc[i2];
            if (vs != 0.0) atomicAdd(&g_acc[i2], vs);
        }
        __threadfence();
        unsigned int old = atomicAdd(&g_done, 1);
        if (old == TOTAL_BLOCKS - 1) {
            volatile double* A = g_acc;
            double tot = 0.0;
            #pragma unroll
            for (int s2 = 0; s2 < 3; s2++) {
                double G2 = (double)c_G[s2] * (double)c_G[s2];
                double M  = 48.0 * G2;
                double nk = fmax(A[12 + s2], 1.0);
                double lb = A[6 + s2] / nk;
                double lo = (A[s2] - A[3 + s2]) / M;
                double lc = A[9 + s2] / (nk * (double)NCC);
                tot += 0.05 * lb + 1.0 * lo + 0.5 * lc;
            }
            out[0] = (float)tot;
            #pragma unroll
            for (int i2 = 0; i2 < 16; i2++) g_acc[i2] = 0.0;
            g_done = 0;
            __threadfence();
        }
    }
}

extern "C" void kernel_launch(void* const* d_in, const int* in_sizes, int n_in,
                              void* d_out, int out_size)
{
    const float* p0  = (const float*)d_in[0];
    const float* p1  = (const float*)d_in[1];
    const float* p2  = (const float*)d_in[2];
    const float* tgt = (const float*)d_in[3];
    float* out = (float*)d_out;

    fused_loss_kernel<<<TOTAL_BLOCKS, BLOCK>>>(p0, p1, p2, tgt, out);
}

// round 17
// speedup vs baseline: 1.0264x; 1.0264x over previous
#include <cuda_runtime.h>
#include <math.h>

#define NT   300
#define NCC  80
#define IMGS 640.0f

#define TOTAL_BLOCKS 441           // 3 blocks / SM, one wave
#define BLOCK 256
#define PAIR_BLOCKS 170            // 170*8 warps * 2 units = 2720 >= 2700
#define OBJ_TOTAL4 100800          // float4 count across all obj channels

// accumulators: [0..2]=sp  [3..5]=objsub  [6..8]=box  [9..11]=cls  [12..14]=nkeep
__device__ double g_acc[16] = {0};
__device__ unsigned int g_done = 0;

__constant__ float c_anchors[3][3][2] = {
    {{10.f,13.f},{16.f,30.f},{33.f,23.f}},
    {{30.f,61.f},{62.f,45.f},{59.f,119.f}},
    {{116.f,90.f},{156.f,198.f},{373.f,326.f}}
};
__constant__ float c_ranchors[3][3][2] = {
    {{1.f/10.f,1.f/13.f},{1.f/16.f,1.f/30.f},{1.f/33.f,1.f/23.f}},
    {{1.f/30.f,1.f/61.f},{1.f/62.f,1.f/45.f},{1.f/59.f,1.f/119.f}},
    {{1.f/116.f,1.f/90.f},{1.f/156.f,1.f/198.f},{1.f/373.f,1.f/326.f}}
};
__constant__ float c_stride[3] = {8.f, 16.f, 32.f};
__constant__ int   c_G[3]      = {80, 40, 20};

__device__ __forceinline__ float sigmoidf(float x) {
    return 1.0f / (1.0f + __expf(-x));
}
// sum of softplus over a float4, one log for four elements
__device__ __forceinline__ float sp4(const float4 v) {
    float m = fmaxf(v.x, 0.f) + fmaxf(v.y, 0.f) + fmaxf(v.z, 0.f) + fmaxf(v.w, 0.f);
    float pr = (1.f + __expf(-fabsf(v.x))) * (1.f + __expf(-fabsf(v.y)))
             * (1.f + __expf(-fabsf(v.z))) * (1.f + __expf(-fabsf(v.w)));
    return m + __logf(pr);
}

template<int GG4>
__device__ __forceinline__ float obj_elem(const float* __restrict__ pred, int j) {
    int plane = j / GG4;              // compile-time divisor
    int w4 = j - plane * GG4;
    const float4 v = *(const float4*)(pred + (long)plane * (340 * GG4) + 4 * w4);
    return sp4(v);
}

// obj softplus for this thread's global slot (same mapping in both roles)
__device__ __forceinline__ void obj_sweep(int i, const float* __restrict__ p0,
                                          const float* __restrict__ p1,
                                          const float* __restrict__ p2,
                                          float osum[3]) {
    if (i < OBJ_TOTAL4) {
        if (i < 76800)       osum[0] += obj_elem<1600>(p0, i);
        else if (i < 96000)  osum[1] += obj_elem<400>(p1, i - 76800);
        else                 osum[2] += obj_elem<100>(p2, i - 96000);
    }
}

__global__ void __launch_bounds__(BLOCK)
fused_loss_kernel(const float* __restrict__ p0,
                  const float* __restrict__ p1,
                  const float* __restrict__ p2,
                  const float* __restrict__ tgt,
                  float* __restrict__ out)
{
    const int tid  = threadIdx.x;
    const int bx   = blockIdx.x;
    const int warp = tid >> 5, lane = tid & 31;

    __shared__ double sacc[15];

    if (bx >= PAIR_BLOCKS) {
        // ======================= OBJ-ONLY BLOCKS (no staging) ==================
        if (tid < 3) sacc[tid] = 0.0;
        __syncthreads();

        float osum[3] = {0.f, 0.f, 0.f};
        obj_sweep(bx * BLOCK + tid, p0, p1, p2, osum);
        #pragma unroll
        for (int s = 0; s < 3; s++) {
            #pragma unroll
            for (int o = 16; o > 0; o >>= 1)
                osum[s] += __shfl_down_sync(0xFFFFFFFF, osum[s], o);
            if (lane == 0 && osum[s] != 0.f) atomicAdd(&sacc[s], (double)osum[s]);
        }
        __syncthreads();

        if (tid == 0) {
            #pragma unroll
            for (int i2 = 0; i2 < 3; i2++) {
                double vs = sacc[i2];
                if (vs != 0.0) atomicAdd(&g_acc[i2], vs);
            }
            __threadfence();
            unsigned int old = atomicAdd(&g_done, 1);
            if (old == TOTAL_BLOCKS - 1) {
                volatile double* A = g_acc;
                double tot = 0.0;
                #pragma unroll
                for (int s2 = 0; s2 < 3; s2++) {
                    double G2 = (double)c_G[s2] * (double)c_G[s2];
                    double M  = 48.0 * G2;
                    double nk = fmax(A[12 + s2], 1.0);
                    tot += 0.05 * (A[6 + s2] / nk)
                         + (A[s2] - A[3 + s2]) / M
                         + 0.5 * (A[9 + s2] / (nk * (double)NCC));
                }
                out[0] = (float)tot;
                #pragma unroll
                for (int i2 = 0; i2 < 16; i2++) g_acc[i2] = 0.0;
                g_done = 0;
                __threadfence();
            }
        }
        return;
    }

    // ======================= PAIR BLOCKS =======================
    __shared__ float  scx[NT], scy[NT], sgw[NT], sgh[NT];   // normalized
    __shared__ short  sbi[NT], scls[NT];
    __shared__ unsigned char sgi[3][NT], sgj[3][NT];
    __shared__ unsigned short skeep[NT];                     // 9 bits: sc*3+a

    if (tid < 15) sacc[tid] = 0.0;

    // ---------------- Phase 0: stage targets ----------------
    for (int n = tid; n < NT; n += BLOCK) {
        float bi = tgt[n * 6 + 0];
        float cl = tgt[n * 6 + 1];
        float tx = tgt[n * 6 + 2];
        float ty = tgt[n * 6 + 3];
        float tw = tgt[n * 6 + 4];
        float th = tgt[n * 6 + 5];
        sbi[n] = (short)bi; scls[n] = (short)cl;
        scx[n] = tx; scy[n] = ty; sgw[n] = tw; sgh[n] = th;
        float gw = tw * IMGS, gh = th * IMGS;
        unsigned bits = 0;
        #pragma unroll
        for (int sc = 0; sc < 3; sc++) {
            const int G = c_G[sc];
            int gi = (int)(tx * (float)G); gi = min(max(gi, 0), G - 1);
            int gj = (int)(ty * (float)G); gj = min(max(gj, 0), G - 1);
            sgi[sc][n] = (unsigned char)gi;
            sgj[sc][n] = (unsigned char)gj;
            #pragma unroll
            for (int a = 0; a < 3; a++) {
                float rw = gw * c_ranchors[sc][a][0];
                float rh = gh * c_ranchors[sc][a][1];
                if (rw < 4.f && rw > 0.25f && rh < 4.f && rh > 0.25f)
                    bits |= (1u << (sc * 3 + a));
            }
        }
        skeep[n] = (unsigned short)bits;
    }
    __syncthreads();

    // ---------------- Phase A: decode 2 units / warp, issue all gathers -------
    const int wg = bx * 8 + warp;             // [0, 1360)
    int usc[2], upa[2], upn[2], upb[2], ucls[2];
    bool ukept[2] = {false, false};
    float uv0[2], uv1[2], uv2[2];
    #pragma unroll
    for (int k = 0; k < 2; k++) {
        int u = wg * 2 + k;
        if (u < 2700) {
            int sc = u / 900;
            int r = u - sc * 900;
            int pa = r / NT, pn = r - pa * NT;
            usc[k] = sc; upa[k] = pa; upn[k] = pn;
            if (skeep[pn] & (1u << (sc * 3 + pa))) {
                ukept[k] = true;
                upb[k] = sbi[pn]; ucls[k] = scls[pn];
                const float* pred = (sc == 0) ? p0 : ((sc == 1) ? p1 : p2);
                const int G  = c_G[sc];
                const int GG = G * G;
                const int gi = sgi[sc][pn], gj = sgj[sc][pn];
                const float* base = pred + ((long)upb[k] * 255 + (long)pa * 85) * GG
                                         + (long)gj * G + gi;
                uv0[k] = __ldg(base + (long)lane * GG);
                uv1[k] = __ldg(base + (long)(lane + 32) * GG);
                uv2[k] = (lane < 21) ? __ldg(base + (long)(lane + 64) * GG) : 0.0f;
            }
        }
    }

    // ---------------- Phase B: obj softplus (covers gather latency) -----------
    {
        float osum[3] = {0.f, 0.f, 0.f};
        obj_sweep(bx * BLOCK + tid, p0, p1, p2, osum);
        #pragma unroll
        for (int s = 0; s < 3; s++) {
            #pragma unroll
            for (int o = 16; o > 0; o >>= 1)
                osum[s] += __shfl_down_sync(0xFFFFFFFF, osum[s], o);
            if (lane == 0 && osum[s] != 0.f) atomicAdd(&sacc[s], (double)osum[s]);
        }
    }

    // ---------------- Phase C: consume both gathers ----------------
    #pragma unroll
    for (int k = 0; k < 2; k++) {
        if (!ukept[k]) continue;              // warp-uniform
        const int sc = usc[k], pa = upa[k], pn = upn[k];
        const int pb = upb[k], pcls = ucls[k];
        const float v0 = uv0[k], v1 = uv1[k], v2 = uv2[k];
        const int   G  = c_G[sc];
        const float stride = c_stride[sc];
        const int gi = sgi[sc][pn], gj = sgj[sc][pn];

        // lane-parallel dedup: any earlier kept target mapping to same cell?
        bool notfirst = false;
        for (int m2b = 0; m2b < pn; m2b += 32) {
            int m2 = m2b + lane;
            bool m = false;
            if (m2 < pn && (skeep[m2] & (1u << (sc * 3 + pa))) &&
                sbi[m2] == pb && sgi[sc][m2] == gi && sgj[sc][m2] == gj)
                m = true;
            if (__any_sync(0xFFFFFFFF, m)) { notfirst = true; break; }
        }

        // cls BCE: per-lane product-of-(1+e^-|x|) + one log
        float mx = 0.f, pr = 1.f, sub = 0.f;
        if (lane >= 5) {
            mx += fmaxf(v0, 0.f);
            pr *= (1.f + __expf(-fabsf(v0)));
            if (lane - 5 == pcls) sub += v0;
        }
        mx += fmaxf(v1, 0.f);
        pr *= (1.f + __expf(-fabsf(v1)));
        if (lane + 27 == pcls) sub += v1;
        if (lane < 21) {
            mx += fmaxf(v2, 0.f);
            pr *= (1.f + __expf(-fabsf(v2)));
            if (lane + 59 == pcls) sub += v2;
        }
        float csum = mx + __logf(pr) - sub;
        #pragma unroll
        for (int o = 16; o > 0; o >>= 1)
            csum += __shfl_down_sync(0xFFFFFFFF, csum, o);

        float obj = __shfl_sync(0xFFFFFFFF, v0, 0);
        float px  = __shfl_sync(0xFFFFFFFF, v0, 1);
        float py  = __shfl_sync(0xFFFFFFFF, v0, 2);
        float pw  = __shfl_sync(0xFFFFFFFF, v0, 3);
        float ph  = __shfl_sync(0xFFFFFFFF, v0, 4);

        if (lane == 0) {
            float cx = scx[pn] * (float)G;
            float cy = scy[pn] * (float)G;
            float pcx = sigmoidf(px) + (float)gi;
            float pcy = sigmoidf(py) + (float)gj;
            float aw = c_anchors[sc][pa][0] / stride;
            float ah = c_anchors[sc][pa][1] / stride;
            float pbw = __expf(fminf(fmaxf(pw, -4.0f), 4.0f)) * aw;
            float pbh = __expf(fminf(fmaxf(ph, -4.0f), 4.0f)) * ah;

            float b1x0 = (pcx - pbw * 0.5f) * stride;
            float b1y0 = (pcy - pbh * 0.5f) * stride;
            float b1x1 = (pcx + pbw * 0.5f) * stride;
            float b1y1 = (pcy + pbh * 0.5f) * stride;

            float tgw = sgw[pn] * (float)G;
            float tgh = sgh[pn] * (float)G;
            float b2x0 = (cx - tgw * 0.5f) * stride;
            float b2y0 = (cy - tgh * 0.5f) * stride;
            float b2x1 = (cx + tgw * 0.5f) * stride;
            float b2y1 = (cy + tgh * 0.5f) * stride;

            const float eps = 1e-7f;
            float w1 = b1x1 - b1x0, h1 = b1y1 - b1y0;
            float w2 = b2x1 - b2x0, h2 = b2y1 - b2y0;
            float ix = fmaxf(fminf(b1x1, b2x1) - fmaxf(b1x0, b2x0), 0.0f);
            float iy = fmaxf(fminf(b1y1, b2y1) - fmaxf(b1y0, b2y0), 0.0f);
            float inter = ix * iy;
            float uni = w1 * h1 + w2 * h2 - inter + eps;
            float iou = inter / uni;
            float cw = fmaxf(b1x1, b2x1) - fminf(b1x0, b2x0);
            float ch = fmaxf(b1y1, b2y1) - fminf(b1y0, b2y0);
            float c2 = cw * cw + ch * ch + eps;
            float dx = b2x0 + b2x1 - b1x0 - b1x1;
            float dy = b2y0 + b2y1 - b1y0 - b1y1;
            float rho2 = (dx * dx + dy * dy) * 0.25f;
            const float k4pi2 = 4.0f / (float)(M_PI * M_PI);
            float da = atanf(w2 / (h2 + eps)) - atanf(w1 / (h1 + eps));
            float vv = k4pi2 * da * da;
            float alpha = vv / (vv - iou + (1.0f + eps));
            float ciou = iou - (rho2 / c2 + vv * alpha);

            atomicAdd(&sacc[12 + sc], 1.0);
            atomicAdd(&sacc[6 + sc],  (double)(1.0f - ciou));
            atomicAdd(&sacc[9 + sc],  (double)csum);
            if (!notfirst) atomicAdd(&sacc[3 + sc], (double)obj);
        }
    }
    __syncthreads();

    // ---------------- tid0-only publish + finalize ----------------
    if (tid == 0) {
        #pragma unroll
        for (int i2 = 0; i2 < 15; i2++) {
            double vs = sacc[i2];
            if (vs != 0.0) atomicAdd(&g_acc[i2], vs);
        }
        __threadfence();
        unsigned int old = atomicAdd(&g_done, 1);
        if (old == TOTAL_BLOCKS - 1) {
            volatile double* A = g_acc;
            double tot = 0.0;
            #pragma unroll
            for (int s2 = 0; s2 < 3; s2++) {
                double G2 = (double)c_G[s2] * (double)c_G[s2];
                double M  = 48.0 * G2;
                double nk = fmax(A[12 + s2], 1.0);
                tot += 0.05 * (A[6 + s2] / nk)
                     + (A[s2] - A[3 + s2]) / M
                     + 0.5 * (A[9 + s2] / (nk * (double)NCC));
            }
            out[0] = (float)tot;
            #pragma unroll
            for (int i2 = 0; i2 < 16; i2++) g_acc[i2] = 0.0;
            g_done = 0;
            __threadfence();
        }
    }
}

extern "C" void kernel_launch(void* const* d_in, const int* in_sizes, int n_in,
                              void* d_out, int out_size)
{
    const float* p0  = (const float*)d_in[0];
    const float* p1  = (const float*)d_in[1];
    const float* p2  = (const float*)d_in[2];
    const float* tgt = (const float*)d_in[3];
    float* out = (float*)d_out;

    fused_loss_kernel<<<TOTAL_BLOCKS, BLOCK>>>(p0, p1, p2, tgt, out);
}